// round 11
// baseline (speedup 1.0000x reference)
#include <cuda_runtime.h>
#include <math.h>

// Problem constants (fixed by the reference)
#define NN      100000
#define EMAX    1600000
#define FIN     128
#define HCC     64          // heads*hid = 2*32
#define OUTC    40
#define NEG     0.2f
#define BN_EPS  1e-5f

// ---------------- scratch (device globals; no runtime allocation) -----------
__device__ float  g_h  [(size_t)NN * HCC];   // h of current layer
__device__ float  g_x1 [(size_t)NN * HCC];   // x1, later xj = max(x1,x2)
__device__ float2 g_asrc[NN];
__device__ float2 g_adst[NN];
__device__ int    g_rowptr[NN + 1];
__device__ int    g_col[EMAX];
__device__ int    g_deg[NN];
__device__ int    g_cur[NN];
__device__ float  g_bns[HCC];
__device__ float  g_bnb[HCC];

// ---------------- small helpers ---------------------------------------------
__device__ __forceinline__ float lrelu(float x) { return fmaxf(x, NEG * x); }

// ---------------- BN fold ----------------------------------------------------
__global__ void k_bnprep(const float* __restrict__ gamma, const float* __restrict__ beta,
                         const float* __restrict__ mean,  const float* __restrict__ var)
{
    int c = threadIdx.x;
    if (c < HCC) {
        float s = gamma[c] * rsqrtf(var[c] + BN_EPS);
        g_bns[c] = s;
        g_bnb[c] = beta[c] - mean[c] * s;
    }
}

// ---------------- CSR build --------------------------------------------------
__global__ void k_zero()
{
    int i = blockIdx.x * blockDim.x + threadIdx.x;
    if (i < NN) { g_deg[i] = 0; g_cur[i] = 0; }
}

__global__ void k_hist(const int* __restrict__ dst, int E)
{
    int i = blockIdx.x * blockDim.x + threadIdx.x;
    if (i < E) atomicAdd(&g_deg[dst[i]], 1);
}

__global__ void k_scan()
{
    __shared__ int sums[1024];
    const int t  = threadIdx.x;
    const int CH = (NN + 1023) / 1024;           // 98
    int b = t * CH;
    int e = b + CH; if (e > NN) e = NN;
    if (b > NN) b = NN;
    int s = 0;
    for (int i = b; i < e; i++) s += g_deg[i];
    sums[t] = s;
    __syncthreads();
    for (int off = 1; off < 1024; off <<= 1) {
        int v = 0;
        if (t >= off) v = sums[t - off];
        __syncthreads();
        sums[t] += v;
        __syncthreads();
    }
    int run = sums[t] - s;                       // exclusive base
    for (int i = b; i < e; i++) { g_rowptr[i] = run; run += g_deg[i]; }
    if (t == 1023) g_rowptr[NN] = run;
}

__global__ void k_scatter(const int* __restrict__ src, const int* __restrict__ dst, int E)
{
    int i = blockIdx.x * blockDim.x + threadIdx.x;
    if (i < E) {
        int d = dst[i];
        int p = atomicAdd(&g_cur[d], 1);
        g_col[g_rowptr[d] + p] = src[i];
    }
}

// ---------------- attention logits per node ---------------------------------
__global__ void k_alpha(const float* __restrict__ h,
                        const float* __restrict__ a_s, const float* __restrict__ a_d)
{
    int warp = (blockIdx.x * blockDim.x + threadIdx.x) >> 5;
    int lane = threadIdx.x & 31;
    if (warp >= NN) return;
    float v0 = h[(size_t)warp * HCC + lane];
    float v1 = h[(size_t)warp * HCC + 32 + lane];
    float s0 = v0 * a_s[lane];
    float s1 = v1 * a_s[32 + lane];
    float d0 = v0 * a_d[lane];
    float d1 = v1 * a_d[32 + lane];
#pragma unroll
    for (int o = 16; o; o >>= 1) {
        s0 += __shfl_xor_sync(0xffffffffu, s0, o);
        s1 += __shfl_xor_sync(0xffffffffu, s1, o);
        d0 += __shfl_xor_sync(0xffffffffu, d0, o);
        d1 += __shfl_xor_sync(0xffffffffu, d1, o);
    }
    if (lane == 0) {
        g_asrc[warp] = make_float2(s0, s1);
        g_adst[warp] = make_float2(d0, d1);
    }
}

// ---------------- GAT aggregation: one warp per destination node -------------
// mode 0: out = elu(bn(res + b))          (layer 1, writes x1)
// mode 1: out = max(out, res + b)         (layer 2 + JK max, out == x1 buffer)
__global__ void k_gat(const float* __restrict__ h, const float* __restrict__ b,
                      float* __restrict__ out, int mode)
{
    const unsigned FULL = 0xffffffffu;
    int n    = (blockIdx.x * blockDim.x + threadIdx.x) >> 5;
    int lane = threadIdx.x & 31;
    if (n >= NN) return;

    int start = g_rowptr[n];
    int end   = g_rowptr[n + 1];
    float2 ad  = g_adst[n];
    float2 asn = g_asrc[n];

    // self-loop logit
    float es0 = lrelu(asn.x + ad.x);
    float es1 = lrelu(asn.y + ad.y);

    // pass 1: segment max
    float m0 = es0, m1 = es1;
    for (int k = start + lane; k < end; k += 32) {
        float2 as = g_asrc[g_col[k]];
        m0 = fmaxf(m0, lrelu(as.x + ad.x));
        m1 = fmaxf(m1, lrelu(as.y + ad.y));
    }
#pragma unroll
    for (int o = 16; o; o >>= 1) {
        m0 = fmaxf(m0, __shfl_xor_sync(FULL, m0, o));
        m1 = fmaxf(m1, __shfl_xor_sync(FULL, m1, o));
    }

    // pass 2: un-normalized weighted sum + denom
    float exs0 = __expf(es0 - m0);
    float exs1 = __expf(es1 - m1);
    float hn0  = h[(size_t)n * HCC + lane];
    float hn1  = h[(size_t)n * HCC + 32 + lane];
    float f0 = exs0 * hn0;       // self-loop message (lane owns channel)
    float f1 = exs1 * hn1;
    float den0 = 0.f, den1 = 0.f;

    for (int base = start; base < end; base += 32) {
        int idx  = base + lane;
        bool v   = idx < end;
        int  s   = v ? g_col[idx] : 0;
        float ex0 = 0.f, ex1 = 0.f;
        if (v) {
            float2 as = g_asrc[s];
            ex0 = __expf(lrelu(as.x + ad.x) - m0);
            ex1 = __expf(lrelu(as.y + ad.y) - m1);
        }
        den0 += ex0;
        den1 += ex1;
        int cnt = end - base; if (cnt > 32) cnt = 32;
        for (int j = 0; j < cnt; j++) {
            int   sj = __shfl_sync(FULL, s,   j);
            float e0 = __shfl_sync(FULL, ex0, j);
            float e1 = __shfl_sync(FULL, ex1, j);
            f0 += e0 * h[(size_t)sj * HCC + lane];
            f1 += e1 * h[(size_t)sj * HCC + 32 + lane];
        }
    }
#pragma unroll
    for (int o = 16; o; o >>= 1) {
        den0 += __shfl_xor_sync(FULL, den0, o);
        den1 += __shfl_xor_sync(FULL, den1, o);
    }
    den0 += exs0;
    den1 += exs1;

    float r0 = f0 / (den0 + 1e-16f);
    float r1 = f1 / (den1 + 1e-16f);

    int c0 = lane, c1 = 32 + lane;
    size_t o0 = (size_t)n * HCC + c0;
    size_t o1 = (size_t)n * HCC + c1;
    if (mode == 0) {
        r0 = (r0 + b[c0]) * g_bns[c0] + g_bnb[c0];
        r1 = (r1 + b[c1]) * g_bns[c1] + g_bnb[c1];
        r0 = r0 > 0.f ? r0 : expm1f(r0);
        r1 = r1 > 0.f ? r1 : expm1f(r1);
        out[o0] = r0;
        out[o1] = r1;
    } else {
        r0 += b[c0];
        r1 += b[c1];
        out[o0] = fmaxf(out[o0], r0);
        out[o1] = fmaxf(out[o1], r1);
    }
}

// ---------------- tiled fp32 GEMM: [N,K] x [K,WC] (+bias) --------------------
// 64-node x CP-col tile, 4x4 micro-tile per thread, K chunked by 64.
template<int K, int CP, int WC, bool BIAS>
__global__ void k_gemm(const float* __restrict__ A, const float* __restrict__ W,
                       const float* __restrict__ bias, float* __restrict__ Out)
{
    __shared__ __align__(16) float Xs[64 * 68];   // [k][node], stride 68
    __shared__ __align__(16) float Ws[64 * CP];   // [k][col]
    const int TX = CP / 4;
    int tid = threadIdx.x;
    int tx = tid % TX, ty = tid / TX;
    int base = blockIdx.x * 64;

    float acc[4][4];
#pragma unroll
    for (int i = 0; i < 4; i++)
#pragma unroll
        for (int j = 0; j < 4; j++) acc[i][j] = 0.f;

    for (int kc = 0; kc < K; kc += 64) {
        for (int idx = tid; idx < 64 * 64; idx += blockDim.x) {
            int nl = idx >> 6, k = idx & 63;
            int node = base + nl;
            float v = (node < NN) ? A[(size_t)node * K + kc + k] : 0.f;
            Xs[k * 68 + nl] = v;
        }
        for (int idx = tid; idx < 64 * CP; idx += blockDim.x) {
            int k = idx / CP, c = idx % CP;
            float v = (c < WC) ? W[(size_t)(kc + k) * WC + c] : 0.f;
            Ws[idx] = v;
        }
        __syncthreads();
#pragma unroll
        for (int k = 0; k < 64; k++) {
            float4 a  = *(const float4*)&Xs[k * 68 + 4 * ty];
            float4 b4 = *(const float4*)&Ws[k * CP + 4 * tx];
            acc[0][0] += a.x * b4.x; acc[0][1] += a.x * b4.y; acc[0][2] += a.x * b4.z; acc[0][3] += a.x * b4.w;
            acc[1][0] += a.y * b4.x; acc[1][1] += a.y * b4.y; acc[1][2] += a.y * b4.z; acc[1][3] += a.y * b4.w;
            acc[2][0] += a.z * b4.x; acc[2][1] += a.z * b4.y; acc[2][2] += a.z * b4.z; acc[2][3] += a.z * b4.w;
            acc[3][0] += a.w * b4.x; acc[3][1] += a.w * b4.y; acc[3][2] += a.w * b4.z; acc[3][3] += a.w * b4.w;
        }
        __syncthreads();
    }

#pragma unroll
    for (int i = 0; i < 4; i++) {
        int node = base + 4 * ty + i;
        if (node >= NN) continue;
#pragma unroll
        for (int j = 0; j < 4; j++) {
            int c = 4 * tx + j;
            if (c < WC) {
                float v = acc[i][j];
                if (BIAS) v += bias[c];
                Out[(size_t)node * WC + c] = v;
            }
        }
    }
}

// ---------------- launcher ---------------------------------------------------
extern "C" void kernel_launch(void* const* d_in, const int* in_sizes, int n_in,
                              void* d_out, int out_size)
{
    const float* node_feat = (const float*)d_in[0];
    const int*   edge      = (const int*)  d_in[1];
    const float* W1        = (const float*)d_in[2];
    const float* a_src1    = (const float*)d_in[3];
    const float* a_dst1    = (const float*)d_in[4];
    const float* b1        = (const float*)d_in[5];
    const float* bn_gamma  = (const float*)d_in[6];
    const float* bn_beta   = (const float*)d_in[7];
    const float* bn_mean   = (const float*)d_in[8];
    const float* bn_var    = (const float*)d_in[9];
    const float* W2        = (const float*)d_in[10];
    const float* a_src2    = (const float*)d_in[11];
    const float* a_dst2    = (const float*)d_in[12];
    const float* b2        = (const float*)d_in[13];
    const float* Wf        = (const float*)d_in[14];
    const float* bf        = (const float*)d_in[15];
    float* outp            = (float*)d_out;

    const int E = in_sizes[1] / 2;
    const int* src = edge;
    const int* dst = edge + E;

    const int GEMM_BLKS = (NN + 63) / 64;          // 1563
    const int WARP_BLKS = (NN + 7) / 8;            // 12500 (8 warps/block)
    const int E_BLKS    = (E + 255) / 256;
    const int N_BLKS    = (NN + 255) / 256;

    // BN fold + CSR build
    k_bnprep<<<1, 64>>>(bn_gamma, bn_beta, bn_mean, bn_var);
    k_zero<<<N_BLKS, 256>>>();
    k_hist<<<E_BLKS, 256>>>(dst, E);
    // overlap-free on one stream; GEMM1 can go before scan (independent)
    k_gemm<FIN, 64, 64, false><<<GEMM_BLKS, 256>>>(node_feat, W1, nullptr, g_h);
    k_scan<<<1, 1024>>>();
    k_scatter<<<E_BLKS, 256>>>(src, dst, E);

    // layer 1
    k_alpha<<<WARP_BLKS, 256>>>(g_h, a_src1, a_dst1);
    k_gat<<<WARP_BLKS, 256>>>(g_h, b1, g_x1, 0);

    // layer 2
    k_gemm<HCC, 64, 64, false><<<GEMM_BLKS, 256>>>(g_x1, W2, nullptr, g_h);
    k_alpha<<<WARP_BLKS, 256>>>(g_h, a_src2, a_dst2);
    k_gat<<<WARP_BLKS, 256>>>(g_h, b2, g_x1, 1);   // writes xj=max(x1,x2) into g_x1

    // final projection 64 -> 40 (+bf)
    k_gemm<HCC, 48, OUTC, true><<<GEMM_BLKS, 192>>>(g_x1, Wf, bf, outp);
}